// round 8
// baseline (speedup 1.0000x reference)
#include <cuda_runtime.h>
#include <math.h>
#include <stdint.h>

#define HIDDEN   2048
#define NEXP     64
#define TOPK     6
#define NGRP     8
#define EPG      8
#define TOPKG    4
#define INTER    1024
#define SHINTER  4096
#define RSCALE   2.5f
#define MAXT     1024
#define ACT_ROWS 14336

#define ASTR 36               // A smem row stride (f32): cols 0-31 data, 32-35 pad (stok/swt live there)
#define BSTR 136              // B smem row stride (f32): frag bank = 8*tg+grp, conflict-free
#define ASZ  (128 * ASTR)     // per-buffer A tile (words)
#define BSZ  (32 * BSTR)      // per-buffer B tile (words)
#define SMEM_BYTES ((2 * ASZ + 2 * BSZ) * 4)   // 71,680 B -> 3 CTAs/SM fit

// fused-kernel CTA counts
#define NB_M0  ((SHINTER / 128) * (MAXT / 128))   // 256
#define NB_M2  ((INTER / 128) * NEXP)             // 512
#define NB_M1  ((HIDDEN / 128) * (MAXT / 128))    // 128
#define NB_M3  ((HIDDEN / 128) * NEXP)            // 1024

// ---------------- scratch ---------------------------------------------------
__device__ int   g_cnt[NEXP];
__device__ int   g_off[NEXP];
__device__ int   g_tok[NEXP * MAXT];
__device__ float g_wt [NEXP * MAXT];
__device__ float g_h1 [MAXT * SHINTER];
__device__ float g_act[(size_t)ACT_ROWS * INTER];

__global__ void k_zero() {
    if (threadIdx.x < NEXP) g_cnt[threadIdx.x] = 0;
}
__global__ void k_scan() {
    if (threadIdx.x == 0) {
        int acc = 0;
        for (int e = 0; e < NEXP; e++) {
            g_off[e] = acc;
            acc += (g_cnt[e] + 127) & ~127;
        }
    }
}

// ---------------- gating ----------------------------------------------------
__global__ void k_gate(const float* __restrict__ x,
                       const float* __restrict__ gw,
                       const float* __restrict__ gb) {
    __shared__ float xs[HIDDEN];
    __shared__ float sc[NEXP];
    __shared__ float sb[NEXP];
    const int t = blockIdx.x;
    const float* xr = x + (size_t)t * HIDDEN;
    for (int i = threadIdx.x; i < HIDDEN / 4; i += blockDim.x)
        ((float4*)xs)[i] = ((const float4*)xr)[i];
    __syncthreads();

    {
        const int e = threadIdx.x;
        const float4* w4 = (const float4*)(gw + (size_t)e * HIDDEN);
        float acc = 0.f;
#pragma unroll 8
        for (int i = 0; i < HIDDEN / 4; i++) {
            float4 wv = w4[i];
            float4 xv = ((float4*)xs)[i];
            acc += wv.x * xv.x + wv.y * xv.y + wv.z * xv.z + wv.w * xv.w;
        }
        float s = 1.f / (1.f + expf(-acc));
        sc[e] = s;
        sb[e] = s + gb[e];
    }
    __syncthreads();

    if (threadIdx.x == 0) {
        float gs[NGRP];
        for (int g = 0; g < NGRP; g++) {
            float m1 = -1e30f, m2 = -1e30f;
            for (int j = 0; j < EPG; j++) {
                float v = sb[g * EPG + j];
                if (v > m1) { m2 = m1; m1 = v; }
                else if (v > m2) { m2 = v; }
            }
            gs[g] = m1 + m2;
        }
        bool gsel[NGRP];
        for (int g = 0; g < NGRP; g++) gsel[g] = false;
        for (int r = 0; r < TOPKG; r++) {
            int bi = -1; float bv = -1e30f;
            for (int g = 0; g < NGRP; g++)
                if (!gsel[g] && gs[g] > bv) { bv = gs[g]; bi = g; }
            gsel[bi] = true;
        }
        bool esel[NEXP];
        for (int e = 0; e < NEXP; e++) esel[e] = false;
        int   eidx[TOPK];
        float wv[TOPK];
        float wsum = 0.f;
        for (int r = 0; r < TOPK; r++) {
            int bi = -1; float bv = -INFINITY;
            for (int e = 0; e < NEXP; e++) {
                if (!gsel[e / EPG] || esel[e]) continue;
                if (sb[e] > bv) { bv = sb[e]; bi = e; }
            }
            esel[bi] = true;
            eidx[r] = bi;
            wv[r] = sc[bi];
            wsum += sc[bi];
        }
        float inv = RSCALE / (wsum + 1e-20f);
        for (int r = 0; r < TOPK; r++) {
            int e = eidx[r];
            int p = atomicAdd(&g_cnt[e], 1);
            g_tok[e * MAXT + p] = t;
            g_wt [e * MAXT + p] = wv[r] * inv;
        }
    }
}

// ---------------- helpers ----------------------------------------------------
__device__ __forceinline__ uint32_t f2tf(float x) {
    uint32_t u;
    asm("cvt.rna.tf32.f32 %0, %1;" : "=r"(u) : "f"(x));
    return u;
}
__device__ __forceinline__ void mma8(float4& d, const uint32_t a[4],
                                     uint32_t b0, uint32_t b1) {
    asm("mma.sync.aligned.m16n8k8.row.col.f32.tf32.tf32.f32 "
        "{%0,%1,%2,%3},{%4,%5,%6,%7},{%8,%9},{%0,%1,%2,%3};"
        : "+f"(d.x), "+f"(d.y), "+f"(d.z), "+f"(d.w)
        : "r"(a[0]), "r"(a[1]), "r"(a[2]), "r"(a[3]), "r"(b0), "r"(b1));
}
__device__ __forceinline__ void cp16(uint32_t smem_addr, const float* gptr) {
    asm volatile("cp.async.cg.shared.global [%0], [%1], 16;"
                 :: "r"(smem_addr), "l"(gptr));
}
__device__ __forceinline__ void cp_commit() {
    asm volatile("cp.async.commit_group;");
}
template <int N>
__device__ __forceinline__ void cp_wait() {
    asm volatile("cp.async.wait_group %0;" :: "n"(N));
}

// ---------------- tf32 GEMM body: BM=128 BN=128 BK=32, 256 thr --------------
// cp.async double-buffered; smem holds raw fp32; f2tf at fragment load.
// __launch_bounds__(256,3) on callers: 3 CTAs/SM (occupancy fix).
// MODE 0: h1 = relu2(x@wup)                  (plain store)
// MODE 1: out += h1@wdn                      (atomicAdd; out pre-zeroed)
// MODE 2: g_act = relu2(Xg@w1[e]) * route_w  (gathered A, plain store)
// MODE 3: out += g_act[e]@w2[e]              (atomic scatter by token)
template <int MODE>
__device__ __forceinline__ void mm_body(int bx, int by,
                                        const float* __restrict__ A,
                                        const float* __restrict__ Bg,
                                        float* __restrict__ C,
                                        int K, int N) {
    extern __shared__ float sm[];
    float* As = sm;                          // [2][ASZ]
    float* Bs = sm + 2 * ASZ;                // [2][BSZ]
    // stok/swt live in A buffer-0 pad columns (words 32/33 of each row; cp.async
    // only writes cols 0..31, fragment loads only read cols 0..31+tg<8)
    int*   stok = (int*)As;                  // stok(r) = stok[r*ASTR+32]
    float* swt  = As;                        // swt (r) = swt [r*ASTR+33]

    const int tid  = threadIdx.x;
    const int lane = tid & 31;
    const int warp = tid >> 5;
    const int wm   = warp & 3;
    const int wn   = warp >> 2;
    const int grp  = lane >> 2;
    const int tg   = lane & 3;
    const int n0   = bx * 128;

    const int arow = tid >> 3;               // 0..31 (+32*i)
    const int acol = (tid & 7) * 4;
    const int brow = tid >> 5;               // 0..7 (+8*i)
    const int bcol = (tid & 31) * 4;

    const uint32_t sA = (uint32_t)__cvta_generic_to_shared(As);
    const uint32_t sB = (uint32_t)__cvta_generic_to_shared(Bs);

    int e = 0, cnt = 0, m_begin, m_end;
    const float* B = Bg;
    const float* Abase = A;
    if (MODE == 0 || MODE == 1) {
        m_begin = by * 128;
        m_end   = m_begin + 128;
    } else {
        e   = by;
        cnt = g_cnt[e];
        if (cnt == 0) return;
        m_begin = 0;
        m_end   = (cnt + 127) & ~127;
        B = Bg + (size_t)e * K * N;
        if (MODE == 3) Abase = A + (size_t)g_off[e] * K;
    }

    for (int m0 = m_begin; m0 < m_end; m0 += 128) {
        if (MODE >= 2) {
            __syncthreads();
            if (tid < 128) {
                int r = m0 + tid;
                int valid = r < cnt;
                stok[tid * ASTR + 32] = g_tok[e * MAXT + (valid ? r : 0)];
                swt [tid * ASTR + 33] = valid ? g_wt[e * MAXT + r] : 0.f;
            }
            __syncthreads();
        }

        uint32_t aofs[4];
#pragma unroll
        for (int i = 0; i < 4; i++) {
            int r = arow + 32 * i;
            if (MODE == 2)      aofs[i] = (uint32_t)stok[r * ASTR + 32] * (uint32_t)K + acol;
            else                aofs[i] = (uint32_t)(m0 + r) * (uint32_t)K + acol;
        }
        const float* abase = Abase;
        const float* bptr = B + (size_t)brow * N + n0 + bcol;

        float4 acc[2][8];
#pragma unroll
        for (int i = 0; i < 2; i++)
#pragma unroll
            for (int j = 0; j < 8; j++) acc[i][j] = make_float4(0.f, 0.f, 0.f, 0.f);

        // prologue: async-load tile 0 into buffer 0
#pragma unroll
        for (int i = 0; i < 4; i++)
            cp16(sA + ((arow + 32 * i) * ASTR + acol) * 4, abase + aofs[i]);
#pragma unroll
        for (int i = 0; i < 4; i++)
            cp16(sB + ((brow + 8 * i) * BSTR + bcol) * 4, bptr + (size_t)(8 * i) * N);
        cp_commit();

        const int NK = K / 32;
        for (int kt = 0; kt < NK; kt++) {
            const int cur = kt & 1;
            if (kt + 1 < NK) {
                const int k0 = (kt + 1) * 32;
                const uint32_t abuf = sA + (cur ^ 1) * ASZ * 4;
                const uint32_t bbuf = sB + (cur ^ 1) * BSZ * 4;
#pragma unroll
                for (int i = 0; i < 4; i++)
                    cp16(abuf + ((arow + 32 * i) * ASTR + acol) * 4, abase + aofs[i] + k0);
#pragma unroll
                for (int i = 0; i < 4; i++)
                    cp16(bbuf + ((brow + 8 * i) * BSTR + bcol) * 4,
                         bptr + (size_t)(k0 + 8 * i) * N);
                cp_commit();
                cp_wait<1>();    // tile kt resident, next tile may be in flight
            } else {
                cp_wait<0>();
            }
            __syncthreads();

            {
                const float* ab = As + cur * ASZ;
                const float* bb = Bs + cur * BSZ;
#pragma unroll
                for (int kk = 0; kk < 32; kk += 8) {
                    uint32_t af[2][4];
#pragma unroll
                    for (int mt = 0; mt < 2; mt++) {
                        int rb = (wm * 32 + mt * 16 + grp) * ASTR + kk;
                        af[mt][0] = f2tf(ab[rb + tg]);
                        af[mt][1] = f2tf(ab[rb + 8 * ASTR + tg]);
                        af[mt][2] = f2tf(ab[rb + tg + 4]);
                        af[mt][3] = f2tf(ab[rb + 8 * ASTR + tg + 4]);
                    }
#pragma unroll
                    for (int nt = 0; nt < 8; nt++) {
                        int cb = (kk + tg) * BSTR + wn * 64 + nt * 8 + grp;
                        uint32_t b0 = f2tf(bb[cb]);
                        uint32_t b1 = f2tf(bb[cb + 4 * BSTR]);
                        mma8(acc[0][nt], af[0], b0, b1);
                        mma8(acc[1][nt], af[1], b0, b1);
                    }
                }
            }
            __syncthreads();   // all reads of buffer `cur` done before it is refilled
        }

        // epilogue
#pragma unroll
        for (int mt = 0; mt < 2; mt++) {
            int r0 = wm * 32 + mt * 16 + grp;
            int r1 = r0 + 8;
#pragma unroll
            for (int nt = 0; nt < 8; nt++) {
                int c = n0 + wn * 64 + nt * 8 + tg * 2;
                float4 v = acc[mt][nt];
                if (MODE == 0 || MODE == 2) {
                    v.x = fmaxf(v.x, 0.f); v.x *= v.x;
                    v.y = fmaxf(v.y, 0.f); v.y *= v.y;
                    v.z = fmaxf(v.z, 0.f); v.z *= v.z;
                    v.w = fmaxf(v.w, 0.f); v.w *= v.w;
                }
                if (MODE == 2) {
                    float w0 = swt[r0 * ASTR + 33], w1 = swt[r1 * ASTR + 33];
                    v.x *= w0; v.y *= w0; v.z *= w1; v.w *= w1;
                }
                if (MODE == 3) {
                    if (m0 + r0 < cnt) {
                        float* o = C + (size_t)stok[r0 * ASTR + 32] * N + c;
                        atomicAdd(o, v.x);
                        atomicAdd(o + 1, v.y);
                    }
                    if (m0 + r1 < cnt) {
                        float* o = C + (size_t)stok[r1 * ASTR + 32] * N + c;
                        atomicAdd(o, v.z);
                        atomicAdd(o + 1, v.w);
                    }
                } else if (MODE == 1) {
                    float* o = C + (size_t)(m0 + r0) * N + c;
                    atomicAdd(o, v.x);
                    atomicAdd(o + 1, v.y);
                    o = C + (size_t)(m0 + r1) * N + c;
                    atomicAdd(o, v.z);
                    atomicAdd(o + 1, v.w);
                } else if (MODE == 2) {
                    float* crow = C + (size_t)(g_off[e] + m0 + r0) * N + c;
                    *(float2*)crow = make_float2(v.x, v.y);
                    crow = C + (size_t)(g_off[e] + m0 + r1) * N + c;
                    *(float2*)crow = make_float2(v.z, v.w);
                } else {
                    *(float2*)(C + (size_t)(m0 + r0) * N + c) = make_float2(v.x, v.y);
                    *(float2*)(C + (size_t)(m0 + r1) * N + c) = make_float2(v.z, v.w);
                }
            }
        }
    }
}

// ---- fused kernel A: mode0 (x->h1) + mode2 (x->g_act), independent ---------
__global__ __launch_bounds__(256, 3) void k_fuseA(const float* __restrict__ x,
                                                  const float* __restrict__ wup,
                                                  float* __restrict__ h1,
                                                  const float* __restrict__ w1,
                                                  float* __restrict__ act) {
    const int bid = blockIdx.x;
    if (bid < NB_M0) {
        mm_body<0>(bid % (SHINTER / 128), bid / (SHINTER / 128),
                   x, wup, h1, HIDDEN, SHINTER);
    } else {
        const int b = bid - NB_M0;
        mm_body<2>(b % (INTER / 128), b / (INTER / 128),
                   x, w1, act, HIDDEN, INTER);
    }
}

// ---- fused kernel B: mode1 (h1->out) + mode3 (act->out), both atomic -------
__global__ __launch_bounds__(256, 3) void k_fuseB(const float* __restrict__ h1,
                                                  const float* __restrict__ wdn,
                                                  const float* __restrict__ act,
                                                  const float* __restrict__ w2,
                                                  float* __restrict__ out) {
    const int bid = blockIdx.x;
    if (bid < NB_M1) {
        mm_body<1>(bid % (HIDDEN / 128), bid / (HIDDEN / 128),
                   h1, wdn, out, SHINTER, HIDDEN);
    } else {
        const int b = bid - NB_M1;
        mm_body<3>(b % (HIDDEN / 128), b / (HIDDEN / 128),
                   act, w2, out, INTER, HIDDEN);
    }
}

// ---------------------------------------------------------------------------
extern "C" void kernel_launch(void* const* d_in, const int* in_sizes, int n_in,
                              void* d_out, int out_size) {
    const float* x   = (const float*)d_in[0];
    const float* gw  = (const float*)d_in[1];
    const float* gb  = (const float*)d_in[2];
    const float* wup = (const float*)d_in[3];
    const float* wdn = (const float*)d_in[4];
    const float* w1  = (const float*)d_in[5];
    const float* w2  = (const float*)d_in[6];
    float* out = (float*)d_out;

    const int T = in_sizes[0] / HIDDEN;      // 1024

    float* h1 = nullptr;
    cudaGetSymbolAddress((void**)&h1, g_h1);
    float* act = nullptr;
    cudaGetSymbolAddress((void**)&act, g_act);

    cudaFuncSetAttribute(k_fuseA, cudaFuncAttributeMaxDynamicSharedMemorySize, SMEM_BYTES);
    cudaFuncSetAttribute(k_fuseB, cudaFuncAttributeMaxDynamicSharedMemorySize, SMEM_BYTES);

    k_zero<<<1, 64>>>();
    k_gate<<<T, 64>>>(x, gw, gb);
    k_scan<<<1, 32>>>();
    cudaMemsetAsync(out, 0, (size_t)out_size * sizeof(float));

    k_fuseA<<<NB_M0 + NB_M2, 256, SMEM_BYTES>>>(x, wup, h1, w1, act);
    k_fuseB<<<NB_M1 + NB_M3, 256, SMEM_BYTES>>>(h1, wdn, act, w2, out);
}

// round 9
// speedup vs baseline: 1.3187x; 1.3187x over previous
#include <cuda_runtime.h>
#include <math.h>
#include <stdint.h>

#define HIDDEN   2048
#define NEXP     64
#define TOPK     6
#define NGRP     8
#define EPG      8
#define TOPKG    4
#define INTER    1024
#define SHINTER  4096
#define RSCALE   2.5f
#define MAXT     1024
#define ACT_ROWS 14336

// fragment-ordered smem layouts
#define A_CH   132                    // A chunk stride (words): 128 data + 4 pad
#define A_TILE (32 * A_CH)            // 32 chunks (4 mb x 2 mt x 4 ks) -> 4224
#define B_CH   640                    // B chunk: 32 lanes x 20 words (16 data + 4 pad)
#define B_TILE (8 * B_CH)             // 8 chunks (2 wn x 4 ks) -> 5120
#define SMEM_WORDS (2 * A_TILE + 2 * B_TILE + 256)
#define SMEM_BYTES (SMEM_WORDS * 4)   // 75,776 B

// fused-kernel CTA counts
#define NB_M0  ((SHINTER / 128) * (MAXT / 128))   // 256
#define NB_M2  ((INTER / 128) * NEXP)             // 512
#define NB_M1  ((HIDDEN / 128) * (MAXT / 128))    // 128
#define NB_M3  ((HIDDEN / 128) * NEXP)            // 1024

// ---------------- scratch ---------------------------------------------------
__device__ int   g_cnt[NEXP];
__device__ int   g_off[NEXP];
__device__ int   g_tok[NEXP * MAXT];
__device__ float g_wt [NEXP * MAXT];
__device__ float g_h1 [MAXT * SHINTER];
__device__ float g_act[(size_t)ACT_ROWS * INTER];

__global__ void k_zero() {
    if (threadIdx.x < NEXP) g_cnt[threadIdx.x] = 0;
}
__global__ void k_scan() {
    if (threadIdx.x == 0) {
        int acc = 0;
        for (int e = 0; e < NEXP; e++) {
            g_off[e] = acc;
            acc += (g_cnt[e] + 127) & ~127;
        }
    }
}

// ---------------- gating ----------------------------------------------------
__global__ void k_gate(const float* __restrict__ x,
                       const float* __restrict__ gw,
                       const float* __restrict__ gb) {
    __shared__ float xs[HIDDEN];
    __shared__ float sc[NEXP];
    __shared__ float sb[NEXP];
    const int t = blockIdx.x;
    const float* xr = x + (size_t)t * HIDDEN;
    for (int i = threadIdx.x; i < HIDDEN / 4; i += blockDim.x)
        ((float4*)xs)[i] = ((const float4*)xr)[i];
    __syncthreads();

    {
        const int e = threadIdx.x;
        const float4* w4 = (const float4*)(gw + (size_t)e * HIDDEN);
        float acc = 0.f;
#pragma unroll 8
        for (int i = 0; i < HIDDEN / 4; i++) {
            float4 wv = w4[i];
            float4 xv = ((float4*)xs)[i];
            acc += wv.x * xv.x + wv.y * xv.y + wv.z * xv.z + wv.w * xv.w;
        }
        float s = 1.f / (1.f + expf(-acc));
        sc[e] = s;
        sb[e] = s + gb[e];
    }
    __syncthreads();

    if (threadIdx.x == 0) {
        float gs[NGRP];
        for (int g = 0; g < NGRP; g++) {
            float m1 = -1e30f, m2 = -1e30f;
            for (int j = 0; j < EPG; j++) {
                float v = sb[g * EPG + j];
                if (v > m1) { m2 = m1; m1 = v; }
                else if (v > m2) { m2 = v; }
            }
            gs[g] = m1 + m2;
        }
        bool gsel[NGRP];
        for (int g = 0; g < NGRP; g++) gsel[g] = false;
        for (int r = 0; r < TOPKG; r++) {
            int bi = -1; float bv = -1e30f;
            for (int g = 0; g < NGRP; g++)
                if (!gsel[g] && gs[g] > bv) { bv = gs[g]; bi = g; }
            gsel[bi] = true;
        }
        bool esel[NEXP];
        for (int e = 0; e < NEXP; e++) esel[e] = false;
        int   eidx[TOPK];
        float wv[TOPK];
        float wsum = 0.f;
        for (int r = 0; r < TOPK; r++) {
            int bi = -1; float bv = -INFINITY;
            for (int e = 0; e < NEXP; e++) {
                if (!gsel[e / EPG] || esel[e]) continue;
                if (sb[e] > bv) { bv = sb[e]; bi = e; }
            }
            esel[bi] = true;
            eidx[r] = bi;
            wv[r] = sc[bi];
            wsum += sc[bi];
        }
        float inv = RSCALE / (wsum + 1e-20f);
        for (int r = 0; r < TOPK; r++) {
            int e = eidx[r];
            int p = atomicAdd(&g_cnt[e], 1);
            g_tok[e * MAXT + p] = t;
            g_wt [e * MAXT + p] = wv[r] * inv;
        }
    }
}

// ---------------- helpers ----------------------------------------------------
__device__ __forceinline__ uint32_t f2tf(float x) {
    uint32_t u;
    asm("cvt.rna.tf32.f32 %0, %1;" : "=r"(u) : "f"(x));
    return u;
}
__device__ __forceinline__ void mma8(float4& d, const uint32_t* a,
                                     uint32_t b0, uint32_t b1) {
    asm("mma.sync.aligned.m16n8k8.row.col.f32.tf32.tf32.f32 "
        "{%0,%1,%2,%3},{%4,%5,%6,%7},{%8,%9},{%0,%1,%2,%3};"
        : "+f"(d.x), "+f"(d.y), "+f"(d.z), "+f"(d.w)
        : "r"(a[0]), "r"(a[1]), "r"(a[2]), "r"(a[3]), "r"(b0), "r"(b1));
}

// Store one staged float4 of A into fragment-ordered smem.
// A element (m,k): chunk ci = ((m/32)*2 + (m%32)/16)*4 + k/8,
//   lane = (m%8)*4 + k%4, reg = ((k%8)/4)*2 + (m%16)/8
//   addr = ci*A_CH + lane*4 + reg
__device__ __forceinline__ void stageA(uint32_t* ab, int arow, int acol,
                                       int i, float4 v) {
    const int ci  = ((i * 2 + (arow >> 4)) << 2) + (acol >> 3);
    const int reg = (((acol >> 2) & 1) << 1) + ((arow >> 3) & 1);
    uint32_t* p = ab + ci * A_CH + ((arow & 7) << 4) + reg;
    p[0]  = f2tf(v.x);
    p[4]  = f2tf(v.y);
    p[8]  = f2tf(v.z);
    p[12] = f2tf(v.w);
}

// Store one staged float4 of B into fragment-ordered smem.
// B element (k,n): chunk cb = (n/64)*4 + k/8,
//   lane = (n%8)*4 + k%4, slot = ((k%8)/4)*8 + (n%64)/8
//   addr = cb*B_CH + lane*20 + slot
__device__ __forceinline__ void stageB(uint32_t* bb, int brow, int bcol,
                                       int i, float4 v) {
    const int cb = ((bcol >> 6) << 2) + i;
    uint32_t* q = bb + cb * B_CH + (((bcol & 7) << 2) + (brow & 3)) * 20
                  + ((brow >> 2) << 3) + ((bcol >> 3) & 7);
    q[0]   = f2tf(v.x);
    q[80]  = f2tf(v.y);
    q[160] = f2tf(v.z);
    q[240] = f2tf(v.w);
}

// ---------------- tf32 GEMM body: BM=128 BN=128 BK=32, 256 thr --------------
// Fragment-ordered smem: all fragment loads are LDS.128, conflict-free.
// Register-staged double buffering, one __syncthreads per k-tile (as R7).
// MODE 0: h1 = relu2(x@wup)                  (plain store)
// MODE 1: out += h1@wdn                      (atomicAdd; out pre-zeroed)
// MODE 2: g_act = relu2(Xg@w1[e]) * route_w  (gathered A, plain store)
// MODE 3: out += g_act[e]@w2[e]              (atomic scatter by token)
template <int MODE>
__device__ __forceinline__ void mm_body(int bx, int by,
                                        const float* __restrict__ A,
                                        const float* __restrict__ Bg,
                                        float* __restrict__ C,
                                        int K, int N) {
    extern __shared__ uint32_t sm[];
    uint32_t* As = sm;                       // [2][A_TILE]
    uint32_t* Bs = sm + 2 * A_TILE;          // [2][B_TILE]
    int*   stok = (int*)(sm + 2 * A_TILE + 2 * B_TILE);
    float* swt  = (float*)(stok + 128);

    const int tid  = threadIdx.x;
    const int lane = tid & 31;
    const int warp = tid >> 5;
    const int wm   = warp & 3;
    const int wn   = warp >> 2;
    const int grp  = lane >> 2;
    const int tg   = lane & 3;
    const int n0   = bx * 128;

    const int arow = tid >> 3;               // 0..31 (+32*i)
    const int acol = (tid & 7) * 4;
    const int brow = tid >> 5;               // 0..7 (+8*i)
    const int bcol = (tid & 31) * 4;

    int e = 0, cnt = 0, m_begin, m_end;
    const float* B = Bg;
    const float* Abase = A;
    if (MODE == 0 || MODE == 1) {
        m_begin = by * 128;
        m_end   = m_begin + 128;
    } else {
        e   = by;
        cnt = g_cnt[e];
        if (cnt == 0) return;
        m_begin = 0;
        m_end   = (cnt + 127) & ~127;
        B = Bg + (size_t)e * K * N;
        if (MODE == 3) Abase = A + (size_t)g_off[e] * K;
    }

    for (int m0 = m_begin; m0 < m_end; m0 += 128) {
        if (MODE >= 2) {
            __syncthreads();
            if (tid < 128) {
                int r = m0 + tid;
                int valid = r < cnt;
                stok[tid] = g_tok[e * MAXT + (valid ? r : 0)];
                swt [tid] = valid ? g_wt[e * MAXT + r] : 0.f;
            }
            __syncthreads();
        }

        uint32_t aofs[4];
#pragma unroll
        for (int i = 0; i < 4; i++) {
            int r = arow + 32 * i;
            if (MODE == 2)      aofs[i] = (uint32_t)stok[r] * (uint32_t)K + acol;
            else                aofs[i] = (uint32_t)(m0 + r) * (uint32_t)K + acol;
        }
        const float* abase = Abase;
        const float* bptr = B + (size_t)brow * N + n0 + bcol;

        float4 acc[2][8];
#pragma unroll
        for (int i = 0; i < 2; i++)
#pragma unroll
            for (int j = 0; j < 8; j++) acc[i][j] = make_float4(0.f, 0.f, 0.f, 0.f);

        float4 ar[4], br[4];
        // prologue: tile 0
#pragma unroll
        for (int i = 0; i < 4; i++) ar[i] = *(const float4*)(abase + aofs[i]);
#pragma unroll
        for (int i = 0; i < 4; i++) br[i] = *(const float4*)(bptr + (size_t)(8 * i) * N);
#pragma unroll
        for (int i = 0; i < 4; i++) stageA(As, arow, acol, i, ar[i]);
#pragma unroll
        for (int i = 0; i < 4; i++) stageB(Bs, brow, bcol, i, br[i]);
        __syncthreads();

        const int NK = K / 32;
        for (int kt = 0; kt < NK; kt++) {
            const int cur = kt & 1;
            const bool more = (kt + 1) < NK;
            if (more) {
                int k0 = (kt + 1) * 32;
#pragma unroll
                for (int i = 0; i < 4; i++)
                    ar[i] = *(const float4*)(abase + aofs[i] + k0);
#pragma unroll
                for (int i = 0; i < 4; i++)
                    br[i] = *(const float4*)(bptr + (size_t)(k0 + 8 * i) * N);
            }
            // compute current buffer (all fragment loads are LDS.128)
            {
                const uint32_t* ab = As + cur * A_TILE;
                const uint32_t* bb = Bs + cur * B_TILE;
#pragma unroll
                for (int ks = 0; ks < 4; ks++) {
                    uint4 a0 = *(const uint4*)(ab + (((wm * 2 + 0) << 2) + ks) * A_CH + lane * 4);
                    uint4 a1 = *(const uint4*)(ab + (((wm * 2 + 1) << 2) + ks) * A_CH + lane * 4);
                    const uint32_t* bbase = bb + ((wn << 2) + ks) * B_CH + lane * 20;
                    uint4 b0lo = *(const uint4*)(bbase);
                    uint4 b0hi = *(const uint4*)(bbase + 4);
                    uint4 b1lo = *(const uint4*)(bbase + 8);
                    uint4 b1hi = *(const uint4*)(bbase + 12);
                    uint32_t b0[8] = {b0lo.x, b0lo.y, b0lo.z, b0lo.w,
                                      b0hi.x, b0hi.y, b0hi.z, b0hi.w};
                    uint32_t b1[8] = {b1lo.x, b1lo.y, b1lo.z, b1lo.w,
                                      b1hi.x, b1hi.y, b1hi.z, b1hi.w};
#pragma unroll
                    for (int nt = 0; nt < 8; nt++) {
                        mma8(acc[0][nt], (const uint32_t*)&a0, b0[nt], b1[nt]);
                        mma8(acc[1][nt], (const uint32_t*)&a1, b0[nt], b1[nt]);
                    }
                }
            }
            if (more) {
                uint32_t* ab = As + (cur ^ 1) * A_TILE;
                uint32_t* bb = Bs + (cur ^ 1) * B_TILE;
#pragma unroll
                for (int i = 0; i < 4; i++) stageA(ab, arow, acol, i, ar[i]);
#pragma unroll
                for (int i = 0; i < 4; i++) stageB(bb, brow, bcol, i, br[i]);
            }
            __syncthreads();
        }

        // epilogue
#pragma unroll
        for (int mt = 0; mt < 2; mt++) {
            int r0 = wm * 32 + mt * 16 + grp;
            int r1 = r0 + 8;
#pragma unroll
            for (int nt = 0; nt < 8; nt++) {
                int c = n0 + wn * 64 + nt * 8 + tg * 2;
                float4 v = acc[mt][nt];
                if (MODE == 0 || MODE == 2) {
                    v.x = fmaxf(v.x, 0.f); v.x *= v.x;
                    v.y = fmaxf(v.y, 0.f); v.y *= v.y;
                    v.z = fmaxf(v.z, 0.f); v.z *= v.z;
                    v.w = fmaxf(v.w, 0.f); v.w *= v.w;
                }
                if (MODE == 2) {
                    float w0 = swt[r0], w1 = swt[r1];
                    v.x *= w0; v.y *= w0; v.z *= w1; v.w *= w1;
                }
                if (MODE == 3) {
                    if (m0 + r0 < cnt) {
                        float* o = C + (size_t)stok[r0] * N + c;
                        atomicAdd(o, v.x);
                        atomicAdd(o + 1, v.y);
                    }
                    if (m0 + r1 < cnt) {
                        float* o = C + (size_t)stok[r1] * N + c;
                        atomicAdd(o, v.z);
                        atomicAdd(o + 1, v.w);
                    }
                } else if (MODE == 1) {
                    float* o = C + (size_t)(m0 + r0) * N + c;
                    atomicAdd(o, v.x);
                    atomicAdd(o + 1, v.y);
                    o = C + (size_t)(m0 + r1) * N + c;
                    atomicAdd(o, v.z);
                    atomicAdd(o + 1, v.w);
                } else if (MODE == 2) {
                    float* crow = C + (size_t)(g_off[e] + m0 + r0) * N + c;
                    *(float2*)crow = make_float2(v.x, v.y);
                    crow = C + (size_t)(g_off[e] + m0 + r1) * N + c;
                    *(float2*)crow = make_float2(v.z, v.w);
                } else {
                    *(float2*)(C + (size_t)(m0 + r0) * N + c) = make_float2(v.x, v.y);
                    *(float2*)(C + (size_t)(m0 + r1) * N + c) = make_float2(v.z, v.w);
                }
            }
        }
    }
}

// ---- fused kernel A: mode0 (x->h1) + mode2 (x->g_act), independent ---------
__global__ __launch_bounds__(256, 2) void k_fuseA(const float* __restrict__ x,
                                                  const float* __restrict__ wup,
                                                  float* __restrict__ h1,
                                                  const float* __restrict__ w1,
                                                  float* __restrict__ act) {
    const int bid = blockIdx.x;
    if (bid < NB_M0) {
        mm_body<0>(bid % (SHINTER / 128), bid / (SHINTER / 128),
                   x, wup, h1, HIDDEN, SHINTER);
    } else {
        const int b = bid - NB_M0;
        mm_body<2>(b % (INTER / 128), b / (INTER / 128),
                   x, w1, act, HIDDEN, INTER);
    }
}

// ---- fused kernel B: mode1 (h1->out) + mode3 (act->out), both atomic -------
__global__ __launch_bounds__(256, 2) void k_fuseB(const float* __restrict__ h1,
                                                  const float* __restrict__ wdn,
                                                  const float* __restrict__ act,
                                                  const float* __restrict__ w2,
                                                  float* __restrict__ out) {
    const int bid = blockIdx.x;
    if (bid < NB_M1) {
        mm_body<1>(bid % (HIDDEN / 128), bid / (HIDDEN / 128),
                   h1, wdn, out, SHINTER, HIDDEN);
    } else {
        const int b = bid - NB_M1;
        mm_body<3>(b % (HIDDEN / 128), b / (HIDDEN / 128),
                   act, w2, out, INTER, HIDDEN);
    }
}

// ---------------------------------------------------------------------------
extern "C" void kernel_launch(void* const* d_in, const int* in_sizes, int n_in,
                              void* d_out, int out_size) {
    const float* x   = (const float*)d_in[0];
    const float* gw  = (const float*)d_in[1];
    const float* gb  = (const float*)d_in[2];
    const float* wup = (const float*)d_in[3];
    const float* wdn = (const float*)d_in[4];
    const float* w1  = (const float*)d_in[5];
    const float* w2  = (const float*)d_in[6];
    float* out = (float*)d_out;

    const int T = in_sizes[0] / HIDDEN;      // 1024

    float* h1 = nullptr;
    cudaGetSymbolAddress((void**)&h1, g_h1);
    float* act = nullptr;
    cudaGetSymbolAddress((void**)&act, g_act);

    cudaFuncSetAttribute(k_fuseA, cudaFuncAttributeMaxDynamicSharedMemorySize, SMEM_BYTES);
    cudaFuncSetAttribute(k_fuseB, cudaFuncAttributeMaxDynamicSharedMemorySize, SMEM_BYTES);

    k_zero<<<1, 64>>>();
    k_gate<<<T, 64>>>(x, gw, gb);
    k_scan<<<1, 32>>>();
    cudaMemsetAsync(out, 0, (size_t)out_size * sizeof(float));

    k_fuseA<<<NB_M0 + NB_M2, 256, SMEM_BYTES>>>(x, wup, h1, w1, act);
    k_fuseB<<<NB_M1 + NB_M3, 256, SMEM_BYTES>>>(h1, wdn, act, w2, out);
}

// round 11
// speedup vs baseline: 2.3966x; 1.8173x over previous
#include <cuda_runtime.h>
#include <cuda_fp16.h>
#include <math.h>
#include <stdint.h>

#define HIDDEN   2048
#define NEXP     64
#define TOPK     6
#define NGRP     8
#define EPG      8
#define TOPKG    4
#define INTER    1024
#define SHINTER  4096
#define RSCALE   2.5f
#define MAXT     1024
#define ACT_ROWS 14336

// half2-packed smem layouts (units: uint32 = half2)
#define AST 20                 // A row stride: 16 data half2 + 4 pad; frag bank 20*grp+tg distinct
#define BST 136                // B k2-row stride: 128 data half2 + 8 pad; frag bank 8*tg+grp distinct
#define A_TILE (128 * AST)     // 2560 words
#define B_TILE (16 * BST)      // 2176 words
#define SMEM_WORDS (2 * A_TILE + 2 * B_TILE + 256)
#define SMEM_BYTES (SMEM_WORDS * 4)   // ~38.9 KB

// fused-kernel CTA counts
#define NB_M0  ((SHINTER / 128) * (MAXT / 128))   // 256
#define NB_M2  ((INTER / 128) * NEXP)             // 512
#define NB_M1  ((HIDDEN / 128) * (MAXT / 128))    // 128
#define NB_M3  ((HIDDEN / 128) * NEXP)            // 1024

// ---------------- scratch ---------------------------------------------------
__device__ int    g_cnt[NEXP];
__device__ int    g_off[NEXP];
__device__ int    g_tok[NEXP * MAXT];
__device__ float  g_wt [NEXP * MAXT];
__device__ __half g_h1 [MAXT * SHINTER];               // fp16 intermediate
__device__ __half g_act[(size_t)ACT_ROWS * INTER];     // fp16 intermediate

__global__ void k_zero() {
    if (threadIdx.x < NEXP) g_cnt[threadIdx.x] = 0;
}
__global__ void k_scan() {
    if (threadIdx.x == 0) {
        int acc = 0;
        for (int e = 0; e < NEXP; e++) {
            g_off[e] = acc;
            acc += (g_cnt[e] + 127) & ~127;
        }
    }
}

// ---------------- gating ----------------------------------------------------
__global__ void k_gate(const float* __restrict__ x,
                       const float* __restrict__ gw,
                       const float* __restrict__ gb) {
    __shared__ float xs[HIDDEN];
    __shared__ float sc[NEXP];
    __shared__ float sb[NEXP];
    const int t = blockIdx.x;
    const float* xr = x + (size_t)t * HIDDEN;
    for (int i = threadIdx.x; i < HIDDEN / 4; i += blockDim.x)
        ((float4*)xs)[i] = ((const float4*)xr)[i];
    __syncthreads();

    {
        const int e = threadIdx.x;
        const float4* w4 = (const float4*)(gw + (size_t)e * HIDDEN);
        float acc = 0.f;
#pragma unroll 8
        for (int i = 0; i < HIDDEN / 4; i++) {
            float4 wv = w4[i];
            float4 xv = ((float4*)xs)[i];
            acc += wv.x * xv.x + wv.y * xv.y + wv.z * xv.z + wv.w * xv.w;
        }
        float s = 1.f / (1.f + expf(-acc));
        sc[e] = s;
        sb[e] = s + gb[e];
    }
    __syncthreads();

    if (threadIdx.x == 0) {
        float gs[NGRP];
        for (int g = 0; g < NGRP; g++) {
            float m1 = -1e30f, m2 = -1e30f;
            for (int j = 0; j < EPG; j++) {
                float v = sb[g * EPG + j];
                if (v > m1) { m2 = m1; m1 = v; }
                else if (v > m2) { m2 = v; }
            }
            gs[g] = m1 + m2;
        }
        bool gsel[NGRP];
        for (int g = 0; g < NGRP; g++) gsel[g] = false;
        for (int r = 0; r < TOPKG; r++) {
            int bi = -1; float bv = -1e30f;
            for (int g = 0; g < NGRP; g++)
                if (!gsel[g] && gs[g] > bv) { bv = gs[g]; bi = g; }
            gsel[bi] = true;
        }
        bool esel[NEXP];
        for (int e = 0; e < NEXP; e++) esel[e] = false;
        int   eidx[TOPK];
        float wv[TOPK];
        float wsum = 0.f;
        for (int r = 0; r < TOPK; r++) {
            int bi = -1; float bv = -INFINITY;
            for (int e = 0; e < NEXP; e++) {
                if (!gsel[e / EPG] || esel[e]) continue;
                if (sb[e] > bv) { bv = sb[e]; bi = e; }
            }
            esel[bi] = true;
            eidx[r] = bi;
            wv[r] = sc[bi];
            wsum += sc[bi];
        }
        float inv = RSCALE / (wsum + 1e-20f);
        for (int r = 0; r < TOPK; r++) {
            int e = eidx[r];
            int p = atomicAdd(&g_cnt[e], 1);
            g_tok[e * MAXT + p] = t;
            g_wt [e * MAXT + p] = wv[r] * inv;
        }
    }
}

// ---------------- helpers ----------------------------------------------------
__device__ __forceinline__ uint32_t packh2(float a, float b) {
    __half2 h = __floats2half2_rn(a, b);   // x=a (low), y=b (high)
    return *(uint32_t*)&h;
}
__device__ __forceinline__ void mma16(float4& d, const uint32_t* a,
                                      uint32_t b0, uint32_t b1) {
    asm("mma.sync.aligned.m16n8k16.row.col.f32.f16.f16.f32 "
        "{%0,%1,%2,%3},{%4,%5,%6,%7},{%8,%9},{%0,%1,%2,%3};"
        : "+f"(d.x), "+f"(d.y), "+f"(d.z), "+f"(d.w)
        : "r"(a[0]), "r"(a[1]), "r"(a[2]), "r"(a[3]), "r"(b0), "r"(b1));
}

// ---------------- fp16 GEMM body: BM=128 BN=128 BK=32, 256 thr --------------
// A smem [row][k2] half2, B smem [k2][n] half2 (k-pair packed).
// Register-staged double buffering, one __syncthreads per k-tile (R7 scheme).
// MODE 0: h1  = relu2(x@wup)            fp16 store
// MODE 1: out += h1@wdn                 fp32 atomicAdd (out pre-zeroed)
// MODE 2: act = relu2(Xg@w1[e])*w       gathered A, fp16 store
// MODE 3: out += act[e]@w2[e]           fp32 atomic scatter by token
// A source: float (MODE 0/2) or half (MODE 1/3).
template <int MODE>
__device__ __forceinline__ void mm_body(int bx, int by,
                                        const void* __restrict__ Av,
                                        const float* __restrict__ Bg,
                                        void* __restrict__ Cv,
                                        int K, int N) {
    extern __shared__ uint32_t sm[];
    uint32_t* As = sm;                        // [2][A_TILE]
    uint32_t* Bs = sm + 2 * A_TILE;           // [2][B_TILE]
    int*   stok = (int*)(sm + 2 * A_TILE + 2 * B_TILE);
    float* swt  = (float*)(stok + 128);

    const int tid  = threadIdx.x;
    const int lane = tid & 31;
    const int warp = tid >> 5;
    const int wm   = warp & 3;
    const int wn   = warp >> 2;
    const int grp  = lane >> 2;
    const int tg   = lane & 3;
    const int n0   = bx * 128;

    // A staging: row = tid>>1 (0..127), h = tid&1 selects k half [16h,16h+16)
    const int arow = tid >> 1;
    const int ah   = tid & 1;
    // B staging: k2 = (tid>>5) + 8i, n4 = (tid&31)*4
    const int bk2  = tid >> 5;
    const int bn4  = (tid & 31) * 4;

    int e = 0, cnt = 0, m_begin, m_end;
    const float* B = Bg;
    if (MODE == 0 || MODE == 1) {
        m_begin = by * 128;
        m_end   = m_begin + 128;
    } else {
        e   = by;
        cnt = g_cnt[e];
        if (cnt == 0) return;
        m_begin = 0;
        m_end   = (cnt + 127) & ~127;
        B = Bg + (size_t)e * K * N;
    }

    const float* Af = (const float*)Av;                 // MODE 0/2
    const __half* Ah = (MODE == 3)
        ? ((const __half*)Av + (size_t)g_off[e] * K)    // MODE 3
        : (const __half*)Av;                            // MODE 1

    for (int m0 = m_begin; m0 < m_end; m0 += 128) {
        if (MODE >= 2) {
            __syncthreads();
            if (tid < 128) {
                int r = m0 + tid;
                int valid = r < cnt;
                stok[tid] = g_tok[e * MAXT + (valid ? r : 0)];
                swt [tid] = valid ? g_wt[e * MAXT + r] : 0.f;
            }
            __syncthreads();
        }

        // A row offset (elements of the source type)
        uint32_t aofs;
        if (MODE == 2)      aofs = (uint32_t)stok[arow] * (uint32_t)K + 16 * ah;
        else                aofs = (uint32_t)(m0 + arow) * (uint32_t)K + 16 * ah;
        const float* bptr = B + (size_t)(2 * bk2) * N + n0 + bn4;

        float4 acc[2][8];
#pragma unroll
        for (int i = 0; i < 2; i++)
#pragma unroll
            for (int j = 0; j < 8; j++) acc[i][j] = make_float4(0.f, 0.f, 0.f, 0.f);

        // staging registers
        float4 arf[4];      // float-A path: 16 floats
        uint4  arh[2];      // half-A path: 16 halves
        float4 brl[2], brh[2];

        // ---- prologue: load tile 0 ----
        if (MODE == 0 || MODE == 2) {
#pragma unroll
            for (int q = 0; q < 4; q++) arf[q] = *(const float4*)(Af + aofs + 4 * q);
        } else {
#pragma unroll
            for (int q = 0; q < 2; q++) arh[q] = *(const uint4*)(Ah + aofs + 8 * q);
        }
#pragma unroll
        for (int i = 0; i < 2; i++) {
            brl[i] = *(const float4*)(bptr + (size_t)(16 * i) * N);
            brh[i] = *(const float4*)(bptr + (size_t)(16 * i + 1) * N);
        }
        // ---- stage into buffer 0 ----
        {
            uint32_t* ab = As;
            uint32_t* bb = Bs;
            uint32_t* pa = ab + arow * AST + 8 * ah;
            if (MODE == 0 || MODE == 2) {
                uint4 w0 = make_uint4(packh2(arf[0].x, arf[0].y), packh2(arf[0].z, arf[0].w),
                                      packh2(arf[1].x, arf[1].y), packh2(arf[1].z, arf[1].w));
                uint4 w1 = make_uint4(packh2(arf[2].x, arf[2].y), packh2(arf[2].z, arf[2].w),
                                      packh2(arf[3].x, arf[3].y), packh2(arf[3].z, arf[3].w));
                *(uint4*)pa = w0;
                *(uint4*)(pa + 4) = w1;
            } else {
                *(uint4*)pa = arh[0];
                *(uint4*)(pa + 4) = arh[1];
            }
#pragma unroll
            for (int i = 0; i < 2; i++) {
                uint4 w = make_uint4(packh2(brl[i].x, brh[i].x), packh2(brl[i].y, brh[i].y),
                                     packh2(brl[i].z, brh[i].z), packh2(brl[i].w, brh[i].w));
                *(uint4*)(bb + (bk2 + 8 * i) * BST + bn4) = w;
            }
        }
        __syncthreads();

        const int NK = K / 32;
        for (int kt = 0; kt < NK; kt++) {
            const int cur = kt & 1;
            const bool more = (kt + 1) < NK;
            if (more) {
                const int k0 = (kt + 1) * 32;
                if (MODE == 0 || MODE == 2) {
#pragma unroll
                    for (int q = 0; q < 4; q++)
                        arf[q] = *(const float4*)(Af + aofs + k0 + 4 * q);
                } else {
#pragma unroll
                    for (int q = 0; q < 2; q++)
                        arh[q] = *(const uint4*)(Ah + aofs + k0 + 8 * q);
                }
#pragma unroll
                for (int i = 0; i < 2; i++) {
                    brl[i] = *(const float4*)(bptr + (size_t)(k0 + 16 * i) * N);
                    brh[i] = *(const float4*)(bptr + (size_t)(k0 + 16 * i + 1) * N);
                }
            }
            // ---- compute current buffer ----
            {
                const uint32_t* ab = As + cur * A_TILE;
                const uint32_t* bb = Bs + cur * B_TILE;
#pragma unroll
                for (int ks = 0; ks < 2; ks++) {
                    uint32_t af[2][4];
#pragma unroll
                    for (int mt = 0; mt < 2; mt++) {
                        const int rb = (wm * 32 + mt * 16 + grp) * AST + 8 * ks + tg;
                        af[mt][0] = ab[rb];
                        af[mt][1] = ab[rb + 8 * AST];
                        af[mt][2] = ab[rb + 4];
                        af[mt][3] = ab[rb + 8 * AST + 4];
                    }
#pragma unroll
                    for (int nt = 0; nt < 8; nt++) {
                        const int cb = (8 * ks + tg) * BST + wn * 64 + nt * 8 + grp;
                        uint32_t b0 = bb[cb];
                        uint32_t b1 = bb[cb + 4 * BST];
                        mma16(acc[0][nt], af[0], b0, b1);
                        mma16(acc[1][nt], af[1], b0, b1);
                    }
                }
            }
            // ---- stage next tile ----
            if (more) {
                uint32_t* ab = As + (cur ^ 1) * A_TILE;
                uint32_t* bb = Bs + (cur ^ 1) * B_TILE;
                uint32_t* pa = ab + arow * AST + 8 * ah;
                if (MODE == 0 || MODE == 2) {
                    uint4 w0 = make_uint4(packh2(arf[0].x, arf[0].y), packh2(arf[0].z, arf[0].w),
                                          packh2(arf[1].x, arf[1].y), packh2(arf[1].z, arf[1].w));
                    uint4 w1 = make_uint4(packh2(arf[2].x, arf[2].y), packh2(arf[2].z, arf[2].w),
                                          packh2(arf[3].x, arf[3].y), packh2(arf[3].z, arf[3].w));
                    *(uint4*)pa = w0;
                    *(uint4*)(pa + 4) = w1;
                } else {
                    *(uint4*)pa = arh[0];
                    *(uint4*)(pa + 4) = arh[1];
                }
#pragma unroll
                for (int i = 0; i < 2; i++) {
                    uint4 w = make_uint4(packh2(brl[i].x, brh[i].x), packh2(brl[i].y, brh[i].y),
                                         packh2(brl[i].z, brh[i].z), packh2(brl[i].w, brh[i].w));
                    *(uint4*)(bb + (bk2 + 8 * i) * BST + bn4) = w;
                }
            }
            __syncthreads();
        }

        // ---- epilogue ----
#pragma unroll
        for (int mt = 0; mt < 2; mt++) {
            int r0 = wm * 32 + mt * 16 + grp;
            int r1 = r0 + 8;
#pragma unroll
            for (int nt = 0; nt < 8; nt++) {
                int c = n0 + wn * 64 + nt * 8 + tg * 2;
                float4 v = acc[mt][nt];
                if (MODE == 0 || MODE == 2) {
                    v.x = fmaxf(v.x, 0.f); v.x *= v.x;
                    v.y = fmaxf(v.y, 0.f); v.y *= v.y;
                    v.z = fmaxf(v.z, 0.f); v.z *= v.z;
                    v.w = fmaxf(v.w, 0.f); v.w *= v.w;
                }
                if (MODE == 2) {
                    float w0 = swt[r0], w1 = swt[r1];
                    v.x *= w0; v.y *= w0; v.z *= w1; v.w *= w1;
                }
                if (MODE == 0) {
                    __half2* Ch = (__half2*)Cv;
                    Ch[((size_t)(m0 + r0) * N + c) >> 1] = __floats2half2_rn(v.x, v.y);
                    Ch[((size_t)(m0 + r1) * N + c) >> 1] = __floats2half2_rn(v.z, v.w);
                } else if (MODE == 2) {
                    __half2* Ch = (__half2*)Cv;
                    Ch[((size_t)(g_off[e] + m0 + r0) * N + c) >> 1] = __floats2half2_rn(v.x, v.y);
                    Ch[((size_t)(g_off[e] + m0 + r1) * N + c) >> 1] = __floats2half2_rn(v.z, v.w);
                } else if (MODE == 1) {
                    float* C = (float*)Cv;
                    float* o = C + (size_t)(m0 + r0) * N + c;
                    atomicAdd(o, v.x);
                    atomicAdd(o + 1, v.y);
                    o = C + (size_t)(m0 + r1) * N + c;
                    atomicAdd(o, v.z);
                    atomicAdd(o + 1, v.w);
                } else {   // MODE 3
                    float* C = (float*)Cv;
                    if (m0 + r0 < cnt) {
                        float* o = C + (size_t)stok[r0] * N + c;
                        atomicAdd(o, v.x);
                        atomicAdd(o + 1, v.y);
                    }
                    if (m0 + r1 < cnt) {
                        float* o = C + (size_t)stok[r1] * N + c;
                        atomicAdd(o, v.z);
                        atomicAdd(o + 1, v.w);
                    }
                }
            }
        }
    }
}

// ---- fused kernel A: mode0 (x->h1) + mode2 (x->act), independent -----------
__global__ __launch_bounds__(256, 2) void k_fuseA(const float* __restrict__ x,
                                                  const float* __restrict__ wup,
                                                  __half* __restrict__ h1,
                                                  const float* __restrict__ w1,
                                                  __half* __restrict__ act) {
    const int bid = blockIdx.x;
    if (bid < NB_M0) {
        mm_body<0>(bid % (SHINTER / 128), bid / (SHINTER / 128),
                   x, wup, h1, HIDDEN, SHINTER);
    } else {
        const int b = bid - NB_M0;
        mm_body<2>(b % (INTER / 128), b / (INTER / 128),
                   x, w1, act, HIDDEN, INTER);
    }
}

// ---- fused kernel B: mode1 (h1->out) + mode3 (act->out), both atomic -------
__global__ __launch_bounds__(256, 2) void k_fuseB(const __half* __restrict__ h1,
                                                  const float* __restrict__ wdn,
                                                  const __half* __restrict__ act,
                                                  const float* __restrict__ w2,
                                                  float* __restrict__ out) {
    const int bid = blockIdx.x;
    if (bid < NB_M1) {
        mm_body<1>(bid % (HIDDEN / 128), bid / (HIDDEN / 128),
                   h1, wdn, out, SHINTER, HIDDEN);
    } else {
        const int b = bid - NB_M1;
        mm_body<3>(b % (HIDDEN / 128), b / (HIDDEN / 128),
                   act, w2, out, INTER, HIDDEN);
    }
}

// ---------------------------------------------------------------------------
extern "C" void kernel_launch(void* const* d_in, const int* in_sizes, int n_in,
                              void* d_out, int out_size) {
    const float* x   = (const float*)d_in[0];
    const float* gw  = (const float*)d_in[1];
    const float* gb  = (const float*)d_in[2];
    const float* wup = (const float*)d_in[3];
    const float* wdn = (const float*)d_in[4];
    const float* w1  = (const float*)d_in[5];
    const float* w2  = (const float*)d_in[6];
    float* out = (float*)d_out;

    const int T = in_sizes[0] / HIDDEN;      // 1024

    __half* h1 = nullptr;
    cudaGetSymbolAddress((void**)&h1, g_h1);
    __half* act = nullptr;
    cudaGetSymbolAddress((void**)&act, g_act);

    cudaFuncSetAttribute(k_fuseA, cudaFuncAttributeMaxDynamicSharedMemorySize, SMEM_BYTES);
    cudaFuncSetAttribute(k_fuseB, cudaFuncAttributeMaxDynamicSharedMemorySize, SMEM_BYTES);

    k_zero<<<1, 64>>>();
    k_gate<<<T, 64>>>(x, gw, gb);
    k_scan<<<1, 32>>>();
    cudaMemsetAsync(out, 0, (size_t)out_size * sizeof(float));

    k_fuseA<<<NB_M0 + NB_M2, 256, SMEM_BYTES>>>(x, wup, h1, w1, act);
    k_fuseB<<<NB_M1 + NB_M3, 256, SMEM_BYTES>>>(h1, wdn, act, w2, out);
}